// round 16
// baseline (speedup 1.0000x reference)
#include <cuda_runtime.h>
#include <cuda_bf16.h>
#include <cstdint>
#include <math.h>

#define MAXT 65536
#define HD   256
#define G3   768
#define NRA  40
#define RNDJ 6        // round 0 fused in k_igf; rounds 1..5 batched; finisher j>=6
#define HBINS 2048
#define EPB  8

// ---------------- device scratch ----------------
__device__ float g_ig[(size_t)MAXT * G3];
__device__ __align__(16) __nv_bfloat16 g_wih_h[G3 * HD];  // Wih gate-interleaved split
__device__ __align__(16) __nv_bfloat16 g_wih_l[G3 * HD];
__device__ __align__(16) __nv_bfloat16 g_wq_h[G3 * HD];   // Whh gate-interleaved split
__device__ __align__(16) __nv_bfloat16 g_wq_l[G3 * HD];
__device__ int g_starts[MAXT + 1];
__device__ int g_len[MAXT];
__device__ int g_sorted[MAXT];
__device__ int g_hist[MAXT + 2];
__device__ int g_suffix[MAXT + 2];
__device__ int g_off[MAXT + 2];
__device__ int g_nact[NRA + 2];
__device__ int g_nep;
__device__ int g_start0;

// ---------------- math helpers ----------------
__device__ __forceinline__ float sigm(float x) {
    x = fminf(15.f, fmaxf(-15.f, x));
    return 1.f / (1.f + __expf(-x));
}
__device__ __forceinline__ float tanhs(float x) {
    x = fminf(9.f, fmaxf(-9.f, x));
    float e = __expf(-2.f * x);
    return (1.f - e) / (1.f + e);
}
__device__ __forceinline__ uint32_t smem_u32(const void* p) {
    uint32_t a;
    asm("{ .reg .u64 t; cvta.to.shared.u64 t, %1; cvt.u32.u64 %0, t; }" : "=r"(a) : "l"(p));
    return a;
}
__device__ __forceinline__ void cpa16(uint32_t s, const void* g) {
    asm volatile("cp.async.cg.shared.global [%0], [%1], 16;"
                 :: "r"(s), "l"(g) : "memory");
}
#define CP_COMMIT() asm volatile("cp.async.commit_group;" ::: "memory")
#define CP_WAIT(n)  asm volatile("cp.async.wait_group %0;" :: "n"(n) : "memory")

__device__ __forceinline__ void ldsm4(uint32_t a, uint32_t* r) {
    asm volatile("ldmatrix.sync.aligned.m8n8.x4.shared.b16 {%0,%1,%2,%3}, [%4];"
                 : "=r"(r[0]), "=r"(r[1]), "=r"(r[2]), "=r"(r[3]) : "r"(a));
}
__device__ __forceinline__ void mma16816(float* c, const uint32_t* a,
                                         uint32_t b0, uint32_t b1) {
    asm volatile("mma.sync.aligned.m16n8k16.row.col.f32.bf16.bf16.f32 "
                 "{%0,%1,%2,%3}, {%4,%5,%6,%7}, {%8,%9}, {%0,%1,%2,%3};"
                 : "+f"(c[0]), "+f"(c[1]), "+f"(c[2]), "+f"(c[3])
                 : "r"(a[0]), "r"(a[1]), "r"(a[2]), "r"(a[3]), "r"(b0), "r"(b1));
}

// Fused 3-term chunk MMA, ONE 16-row m-subtile per warp (16-warp kernels).
template<int NG>
__device__ __forceinline__ void mma_fused1(uint32_t ah, uint32_t al,
                                           uint32_t bh, uint32_t bl,
                                           float (&acc)[4 * NG][4],
                                           int lane, int wm, int wn) {
    int arow = wm * 16 + (lane & 7) + (((lane >> 3) & 1) << 3);
    int aks  = (lane >> 4) & 1;
    int axor = arow & 7;
    uint32_t ahB = ah + arow * 128, alB = al + arow * 128;
    int brow0 = (lane & 7) + (((lane >> 4) & 1) << 3);
    int bks  = (lane >> 3) & 1;
#pragma unroll
    for (int ks = 0; ks < 4; ks++) {
        uint32_t au = (uint32_t)(((2 * ks + aks) ^ axor) << 4);
        uint32_t AH0[4], AL0[4];
        ldsm4(ahB + au, AH0);
        ldsm4(alB + au, AL0);
#pragma unroll
        for (int g = 0; g < NG; g++) {
            int brow = wn * (32 * NG) + g * 32 + brow0;
            int bxor = brow & 7;
            uint32_t bu = (uint32_t)(((2 * ks + bks) ^ bxor) << 4);
            uint32_t bb = (uint32_t)(brow * 128);
            uint32_t BH0[4], BH1[4], BL0[4], BL1[4];
            ldsm4(bh + bb + bu,        BH0);
            ldsm4(bh + bb + 2048 + bu, BH1);
            ldsm4(bl + bb + bu,        BL0);
            ldsm4(bl + bb + 2048 + bu, BL1);
            int nb = g * 4;
            mma16816(acc[nb+0], AH0, BH0[0], BH0[1]);
            mma16816(acc[nb+1], AH0, BH0[2], BH0[3]);
            mma16816(acc[nb+2], AH0, BH1[0], BH1[1]);
            mma16816(acc[nb+3], AH0, BH1[2], BH1[3]);
            mma16816(acc[nb+0], AH0, BL0[0], BL0[1]);
            mma16816(acc[nb+1], AH0, BL0[2], BL0[3]);
            mma16816(acc[nb+2], AH0, BL1[0], BL1[1]);
            mma16816(acc[nb+3], AH0, BL1[2], BL1[3]);
            mma16816(acc[nb+0], AL0, BH0[0], BH0[1]);
            mma16816(acc[nb+1], AL0, BH0[2], BH0[3]);
            mma16816(acc[nb+2], AL0, BH1[0], BH1[1]);
            mma16816(acc[nb+3], AL0, BH1[2], BH1[3]);
        }
    }
}

// ---------------- shared layout (k_igf and k_hg2): 2 stages + conv + s_t --------
#define HG2_A32 0
#define HG2_BH  32768
#define HG2_BL  57344
#define HG2_STRIDE 81920
#define HG2_CAH 163840
#define HG2_CAL 180224
#define HG2_T   196608
#define HG2_SMEM 197120
#define CSTRIDE 196
#define HG2_THREADS 512

// ---------------- setup body (1024-thread block) ----------------
__device__ __forceinline__ int warp_scan_incl(int v, int lane) {
#pragma unroll
    for (int o = 1; o < 32; o <<= 1) {
        int n = __shfl_up_sync(0xFFFFFFFFu, v, o);
        if (lane >= o) v += n;
    }
    return v;
}
__device__ void setup_body(const int* __restrict__ start, int T) {
    __shared__ int s_w[32];
    __shared__ int s_hist[HBINS];
    __shared__ int s_lmax;
    int tid = threadIdx.x, lane = tid & 31, w = tid >> 5;
    int per = (T + 1023) / 1024;
    int b0 = tid * per, b1 = min(T, b0 + per);

    int c = 0;
    for (int t = b0; t < b1; t++)
        if (t == 0 || start[t] != 0) c++;
    int inc = warp_scan_incl(c, lane);
    if (lane == 31) s_w[w] = inc;
    __syncthreads();
    if (w == 0) s_w[lane] = warp_scan_incl(s_w[lane], lane);
    __syncthreads();
    int excl = inc - c + (w ? s_w[w - 1] : 0);
    int nep = s_w[31];
    if (tid == 0) { g_nep = nep; g_start0 = (start[0] != 0); s_lmax = 0; }

    int e = excl;
    for (int t = b0; t < b1; t++)
        if (t == 0 || start[t] != 0) g_starts[e++] = t;
    if (tid == 0) g_starts[nep] = T;
    for (int b = tid; b < HBINS; b += 1024) s_hist[b] = 0;
    __syncthreads();

    for (int e2 = tid; e2 < nep; e2 += 1024) {
        int L = g_starts[e2 + 1] - g_starts[e2];
        g_len[e2] = L;
        if (L < HBINS) atomicAdd(&s_hist[L], 1);
        atomicMax(&s_lmax, L);
    }
    __syncthreads();
    int Lmax = s_lmax;
    int NB = Lmax + 2;

    for (int b = tid; b < NB; b += 1024) g_hist[b] = 0;
    __syncthreads();
    for (int b = tid; b < min(NB, HBINS); b += 1024)
        if (s_hist[b]) g_hist[b] = s_hist[b];
    if (Lmax >= HBINS) {
        __syncthreads();
        for (int e2 = tid; e2 < nep; e2 += 1024) {
            int L = g_len[e2];
            if (L >= HBINS) atomicAdd(&g_hist[L], 1);
        }
    }
    __syncthreads();

    int per2 = (NB + 1023) / 1024;
    int c0 = tid * per2, c1 = min(NB, c0 + per2);
    int s = 0;
    for (int b = c0; b < c1; b++) s += g_hist[b];
    int inc2 = warp_scan_incl(s, lane);
    if (lane == 31) s_w[w] = inc2;
    __syncthreads();
    if (w == 0) s_w[lane] = warp_scan_incl(s_w[lane], lane);
    __syncthreads();
    int incl_full = inc2 + (w ? s_w[w - 1] : 0);
    int total2 = s_w[31];
    int run = total2 - incl_full;
    for (int b = c1 - 1; b >= c0; b--) { run += g_hist[b]; g_suffix[b] = run; }
    __syncthreads();

    for (int b = tid; b <= Lmax; b += 1024) g_off[b] = g_suffix[b + 1];
    for (int j = tid; j <= NRA; j += 1024)
        g_nact[j] = (j + 1 <= Lmax + 1) ? g_suffix[j + 1] : 0;
    __syncthreads();
    for (int e2 = tid; e2 < nep; e2 += 1024) {
        int L = g_len[e2];
        int p = atomicAdd(&g_off[L], 1);
        g_sorted[p] = e2;
    }
}

// ---------------- split (weights only, both gate-interleaved) + setup ------------
__global__ void __launch_bounds__(1024) k_split(const float* __restrict__ wih,
                                                const float* __restrict__ whh,
                                                const int* __restrict__ start, int T) {
    int b = blockIdx.x;
    if (b < 192) {
        int i = b * 1024 + threadIdx.x;
        int q = i >> 8, k = i & 255;
        int nt = q / 192, rem = q % 192;
        int gg = rem >> 6, il = rem & 63;
        size_t src = (size_t)(gg * 256 + nt * 64 + il) * HD + k;
        float v = wih[src];
        __nv_bfloat16 h = __float2bfloat16(v);
        g_wih_h[i] = h;
        g_wih_l[i] = __float2bfloat16(v - __bfloat162float(h));
        float w = whh[src];
        __nv_bfloat16 hh = __float2bfloat16(w);
        g_wq_h[i] = hh;
        g_wq_l[i] = __float2bfloat16(w - __bfloat162float(hh));
    } else {
        setup_body(start, T);
    }
}

// ---------------- generic A-issue / convert (fp32 rows -> bf16 hi/lo smem) -------
__device__ __forceinline__ void a_convert(char* smem, int stage, int tid) {
    const float* a32 = (const float*)(smem + stage * HG2_STRIDE + HG2_A32);
#pragma unroll
    for (int v = tid; v < 1024; v += HG2_THREADS) {
        int r = v >> 3, u = v & 7;
        float4 f0 = *(const float4*)(a32 + r * 64 + u * 8);
        float4 f1 = *(const float4*)(a32 + r * 64 + u * 8 + 4);
        float fv[8] = {f0.x, f0.y, f0.z, f0.w, f1.x, f1.y, f1.z, f1.w};
        __nv_bfloat16 hi[8], lo[8];
#pragma unroll
        for (int q = 0; q < 8; q++) {
            hi[q] = __float2bfloat16(fv[q]);
            lo[q] = __float2bfloat16(fv[q] - __bfloat162float(hi[q]));
        }
        uint32_t off = (uint32_t)(r * 128 + (((u ^ (r & 7))) << 4));
        *(uint4*)(smem + HG2_CAH + off) = *(const uint4*)hi;
        *(uint4*)(smem + HG2_CAL + off) = *(const uint4*)lo;
    }
}

// ---------------- fused igates + round-0 gates kernel ----------------------------
__device__ __forceinline__ void igf_issue(uint32_t sb, int stage, int c,
                                          const float* x, int mt0, int nt, int tid,
                                          const __nv_bfloat16* bh,
                                          const __nv_bfloat16* bl) {
    uint32_t st = sb + stage * HG2_STRIDE;
    int cb = c * 64;
#pragma unroll
    for (int v = tid; v < 2048; v += HG2_THREADS) {
        int r = v >> 4, u = v & 15;
        cpa16(st + HG2_A32 + r * 256 + u * 16,
              x + (size_t)(mt0 + r) * HD + cb + u * 4);
    }
#pragma unroll
    for (int v = tid; v < 1536; v += HG2_THREADS) {
        int r = v >> 3, u = v & 7;
        uint32_t off = (uint32_t)(r * 128 + (((u ^ (r & 7))) << 4));
        size_t src = (size_t)(nt * 192 + r) * HD + cb + u * 8;
        cpa16(st + HG2_BH + off, bh + src);
        cpa16(st + HG2_BL + off, bl + src);
    }
    CP_COMMIT();
}
__global__ void __launch_bounds__(HG2_THREADS, 1) k_igf(const float* __restrict__ x,
                                                        const int* __restrict__ start,
                                                        const float* __restrict__ bias,
                                                        const float* __restrict__ bias_n,
                                                        float* __restrict__ y) {
    extern __shared__ __align__(128) char smem[];
    uint32_t sb = smem_u32(smem);
    int mt0 = blockIdx.y * 128;
    int tid = threadIdx.x, lane = tid & 31, wid = tid >> 5;
    int wm = wid >> 1, wn = wid & 1;
    int nt = blockIdx.x;

    float acc[12][4];
#pragma unroll
    for (int b = 0; b < 12; b++)
#pragma unroll
        for (int cdx = 0; cdx < 4; cdx++) acc[b][cdx] = 0.f;

    igf_issue(sb, 0, 0, x, mt0, nt, tid, g_wih_h, g_wih_l);
    igf_issue(sb, 1, 1, x, mt0, nt, tid, g_wih_h, g_wih_l);

    CP_WAIT(1); __syncthreads();
    a_convert(smem, 0, tid); __syncthreads();
    mma_fused1<3>(sb + HG2_CAH, sb + HG2_CAL,
                  sb + 0 * HG2_STRIDE + HG2_BH, sb + 0 * HG2_STRIDE + HG2_BL,
                  acc, lane, wm, wn);
    __syncthreads();
    igf_issue(sb, 0, 2, x, mt0, nt, tid, g_wih_h, g_wih_l);

    CP_WAIT(1); __syncthreads();
    a_convert(smem, 1, tid); __syncthreads();
    mma_fused1<3>(sb + HG2_CAH, sb + HG2_CAL,
                  sb + 1 * HG2_STRIDE + HG2_BH, sb + 1 * HG2_STRIDE + HG2_BL,
                  acc, lane, wm, wn);
    __syncthreads();
    igf_issue(sb, 1, 3, x, mt0, nt, tid, g_wih_h, g_wih_l);

    CP_WAIT(1); __syncthreads();
    a_convert(smem, 0, tid); __syncthreads();
    mma_fused1<3>(sb + HG2_CAH, sb + HG2_CAL,
                  sb + 0 * HG2_STRIDE + HG2_BH, sb + 0 * HG2_STRIDE + HG2_BL,
                  acc, lane, wm, wn);

    CP_WAIT(0); __syncthreads();
    a_convert(smem, 1, tid); __syncthreads();
    mma_fused1<3>(sb + HG2_CAH, sb + HG2_CAL,
                  sb + 1 * HG2_STRIDE + HG2_BH, sb + 1 * HG2_STRIDE + HG2_BL,
                  acc, lane, wm, wn);
    __syncthreads();

    // stage C
    float* C = (float*)smem;
#pragma unroll
    for (int ntv = 0; ntv < 12; ntv++) {
        int g = ntv >> 2, ntl = ntv & 3;
        int col = wn * 96 + g * 32 + ntl * 8 + (lane & 3) * 2;
        int row = wm * 16 + (lane >> 2);
        C[row * CSTRIDE + col]           = acc[ntv][0];
        C[row * CSTRIDE + col + 1]       = acc[ntv][1];
        C[(row + 8) * CSTRIDE + col]     = acc[ntv][2];
        C[(row + 8) * CSTRIDE + col + 1] = acc[ntv][3];
    }
    __syncthreads();

    // epilogue: start rows -> gate + write y ; other rows -> write biased ig
    int start0 = g_start0;
#pragma unroll 1
    for (int idx = tid; idx < 2048; idx += HG2_THREADS) {
        int row = idx >> 4, q4 = idx & 15;
        int t = mt0 + row;
        int i = nt * 64 + q4 * 4;
        const float* cr = C + row * CSTRIDE + q4 * 4;
        float4 rp = *(const float4*)(cr);
        float4 zp = *(const float4*)(cr + 64);
        float4 np = *(const float4*)(cr + 128);
        float4 br4 = *(const float4*)(bias + i);
        float4 bz4 = *(const float4*)(bias + HD + i);
        float4 bn4p = *(const float4*)(bias + 2 * HD + i);
        float igr[4] = {rp.x + br4.x, rp.y + br4.y, rp.z + br4.z, rp.w + br4.w};
        float igz[4] = {zp.x + bz4.x, zp.y + bz4.y, zp.z + bz4.z, zp.w + bz4.w};
        float ign[4] = {np.x + bn4p.x, np.y + bn4p.y, np.z + bn4p.z, np.w + bn4p.w};
        int is_start = (t == 0) ? start0 : start[t];
        if (is_start) {
            float4 bn4 = *(const float4*)(bias_n + i);
            float bnv[4] = {bn4.x, bn4.y, bn4.z, bn4.w};
            float o[4];
#pragma unroll
            for (int u = 0; u < 4; u++) {
                float r = sigm(igr[u]);
                float z = sigm(igz[u]);
                float n = tanhs(ign[u] + r * bnv[u]);
                o[u] = n * (1.f - z);
            }
            *(float4*)(y + (size_t)t * HD + i) = make_float4(o[0], o[1], o[2], o[3]);
        } else {
            float* igrow = g_ig + (size_t)t * G3;
            *(float4*)(igrow + i)          = make_float4(igr[0], igr[1], igr[2], igr[3]);
            *(float4*)(igrow + HD + i)     = make_float4(igz[0], igz[1], igz[2], igz[3]);
            *(float4*)(igrow + 2 * HD + i) = make_float4(ign[0], ign[1], ign[2], ign[3]);
        }
    }
}

// ---------------- fused round kernel (512 threads, 16 warps, 8m x 2n) -----------
__device__ __forceinline__ void hg2_issue(uint32_t sb, char* smem, int stage, int c,
                                          const float* y, int nt, int tid) {
    uint32_t st = sb + stage * HG2_STRIDE;
    const int* s_t = (const int*)(smem + HG2_T);
    int cb = c * 64;
#pragma unroll
    for (int v = tid; v < 2048; v += HG2_THREADS) {
        int r = v >> 4, u = v & 15;
        const float* src = y + (size_t)(s_t[r] - 1) * HD + cb + u * 4;
        cpa16(st + HG2_A32 + r * 256 + u * 16, src);
    }
#pragma unroll
    for (int v = tid; v < 1536; v += HG2_THREADS) {
        int r = v >> 3, u = v & 7;
        uint32_t off = (uint32_t)(r * 128 + (((u ^ (r & 7))) << 4));
        size_t src = (size_t)(nt * 192 + r) * HD + cb + u * 8;
        cpa16(st + HG2_BH + off, g_wq_h + src);
        cpa16(st + HG2_BL + off, g_wq_l + src);
    }
    CP_COMMIT();
}
__global__ void __launch_bounds__(HG2_THREADS, 1) k_hg2(float* __restrict__ y,
                                                        const float* __restrict__ bias_n,
                                                        int j) {
    extern __shared__ __align__(128) char smem[];
    uint32_t sb = smem_u32(smem);
    int* s_t = (int*)(smem + HG2_T);
    int nj = g_nact[j];
    int mt0 = blockIdx.y * 128;
    if (mt0 >= nj) return;
    int tid = threadIdx.x, lane = tid & 31, wid = tid >> 5;
    int wm = wid >> 1, wn = wid & 1;
    int nt = blockIdx.x;

    if (tid < 128) {
        int m = mt0 + tid;
        s_t[tid] = (m < nj) ? (g_starts[g_sorted[m]] + j) : 1;
    }
    __syncthreads();

    float acc[12][4];
#pragma unroll
    for (int b = 0; b < 12; b++)
#pragma unroll
        for (int cdx = 0; cdx < 4; cdx++) acc[b][cdx] = 0.f;

    hg2_issue(sb, smem, 0, 0, y, nt, tid);
    hg2_issue(sb, smem, 1, 1, y, nt, tid);

    CP_WAIT(1); __syncthreads();
    a_convert(smem, 0, tid); __syncthreads();
    mma_fused1<3>(sb + HG2_CAH, sb + HG2_CAL,
                  sb + 0 * HG2_STRIDE + HG2_BH, sb + 0 * HG2_STRIDE + HG2_BL,
                  acc, lane, wm, wn);
    __syncthreads();
    hg2_issue(sb, smem, 0, 2, y, nt, tid);

    CP_WAIT(1); __syncthreads();
    a_convert(smem, 1, tid); __syncthreads();
    mma_fused1<3>(sb + HG2_CAH, sb + HG2_CAL,
                  sb + 1 * HG2_STRIDE + HG2_BH, sb + 1 * HG2_STRIDE + HG2_BL,
                  acc, lane, wm, wn);
    __syncthreads();
    hg2_issue(sb, smem, 1, 3, y, nt, tid);

    CP_WAIT(1); __syncthreads();
    a_convert(smem, 0, tid); __syncthreads();
    mma_fused1<3>(sb + HG2_CAH, sb + HG2_CAL,
                  sb + 0 * HG2_STRIDE + HG2_BH, sb + 0 * HG2_STRIDE + HG2_BL,
                  acc, lane, wm, wn);

    CP_WAIT(0); __syncthreads();
    a_convert(smem, 1, tid); __syncthreads();
    mma_fused1<3>(sb + HG2_CAH, sb + HG2_CAL,
                  sb + 1 * HG2_STRIDE + HG2_BH, sb + 1 * HG2_STRIDE + HG2_BL,
                  acc, lane, wm, wn);
    __syncthreads();

    float* C = (float*)smem;
#pragma unroll
    for (int ntv = 0; ntv < 12; ntv++) {
        int g = ntv >> 2, ntl = ntv & 3;
        int col = wn * 96 + g * 32 + ntl * 8 + (lane & 3) * 2;
        int row = wm * 16 + (lane >> 2);
        C[row * CSTRIDE + col]           = acc[ntv][0];
        C[row * CSTRIDE + col + 1]       = acc[ntv][1];
        C[(row + 8) * CSTRIDE + col]     = acc[ntv][2];
        C[(row + 8) * CSTRIDE + col + 1] = acc[ntv][3];
    }
    __syncthreads();

#pragma unroll 1
    for (int idx = tid; idx < 2048; idx += HG2_THREADS) {
        int row = idx >> 4, q4 = idx & 15;
        if (mt0 + row >= nj) continue;
        int t = s_t[row];
        int i = nt * 64 + q4 * 4;
        const float* cr = C + row * CSTRIDE + q4 * 4;
        float4 rp = *(const float4*)(cr);
        float4 zp = *(const float4*)(cr + 64);
        float4 np = *(const float4*)(cr + 128);
        const float* igrow = g_ig + (size_t)t * G3;
        float4 igr = *(const float4*)(igrow + i);
        float4 igz = *(const float4*)(igrow + HD + i);
        float4 ign = *(const float4*)(igrow + 2 * HD + i);
        float4 h4  = *(const float4*)(y + (size_t)(t - 1) * HD + i);
        float4 bn4 = *(const float4*)(bias_n + i);
        float rv[4] = {rp.x, rp.y, rp.z, rp.w};
        float zv[4] = {zp.x, zp.y, zp.z, zp.w};
        float nv[4] = {np.x, np.y, np.z, np.w};
        float ir[4] = {igr.x, igr.y, igr.z, igr.w};
        float iz[4] = {igz.x, igz.y, igz.z, igz.w};
        float in_[4] = {ign.x, ign.y, ign.z, ign.w};
        float hv[4] = {h4.x, h4.y, h4.z, h4.w};
        float bv[4] = {bn4.x, bn4.y, bn4.z, bn4.w};
        float o[4];
#pragma unroll
        for (int u = 0; u < 4; u++) {
            float r = sigm(ir[u] + rv[u]);
            float z = sigm(iz[u] + zv[u]);
            float n = tanhs(in_[u] + r * (nv[u] + bv[u]));
            o[u] = n + z * (hv[u] - n);
        }
        *(float4*)(y + (size_t)t * HD + i) = make_float4(o[0], o[1], o[2], o[3]);
    }
}

// ---------------- episode-0 round-0 (h = state), parallel ----------------
__global__ void k_ep0(float* __restrict__ y, const float* __restrict__ state,
                      const float* __restrict__ Whh, const float* __restrict__ bias_n) {
    if (g_start0) return;   // fused path handled t=0 (h=0)
    __shared__ float sh[HD];
    int tid = threadIdx.x;
    sh[tid] = state[tid];
    __syncthreads();
    int u = tid >> 3, s = tid & 7;
    int i = blockIdx.x * 32 + u;
    const float4* h4 = (const float4*)(sh + s * 32);
    float p[3];
#pragma unroll
    for (int g = 0; g < 3; g++) {
        const float4* w = (const float4*)(Whh + (size_t)(g * HD + i) * HD + s * 32);
        float acc = 0.f;
#pragma unroll
        for (int k = 0; k < 8; k++) {
            float4 hv = h4[k], wv = w[k];
            acc = fmaf(hv.x, wv.x, acc); acc = fmaf(hv.y, wv.y, acc);
            acc = fmaf(hv.z, wv.z, acc); acc = fmaf(hv.w, wv.w, acc);
        }
#pragma unroll
        for (int o = 4; o >= 1; o >>= 1)
            acc += __shfl_down_sync(0xFFFFFFFFu, acc, o);
        p[g] = acc;
    }
    if (s == 0) {
        const float* ig = g_ig;   // t = 0 (written by k_igf: non-start row)
        float h = sh[i];
        float r = sigm(ig[i] + p[0]);
        float z = sigm(ig[HD + i] + p[1]);
        float n = tanhs(ig[2 * HD + i] + r * (p[2] + bias_n[i]));
        y[i] = n + z * (h - n);
    }
}

// ---------------- finisher: 8 sorted-adjacent episodes per block, lockstep ------
__global__ void __launch_bounds__(256) k_finish8(const float* __restrict__ Whh,
                                                 const float* __restrict__ bias_n,
                                                 float* y) {
    int nover = g_nact[RNDJ];
    __shared__ __align__(16) float sh[EPB][HD];
    __shared__ int s_ts[EPB], s_len[EPB], s_lmax;
    int i = threadIdx.x;
    const float4* w0 = (const float4*)(Whh + (size_t)i * HD);
    const float4* w1 = (const float4*)(Whh + (size_t)(HD + i) * HD);
    const float4* w2 = (const float4*)(Whh + (size_t)(2 * HD + i) * HD);
    float bn = bias_n[i];

    for (int g0 = blockIdx.x * EPB; g0 < nover; g0 += gridDim.x * EPB) {
        if (i == 0) s_lmax = 0;
        __syncthreads();
        if (i < EPB) {
            int idx = g0 + i;
            if (idx < nover) {
                int e = g_sorted[idx];
                s_ts[i] = g_starts[e];
                s_len[i] = g_len[e];
                atomicMax(&s_lmax, g_len[e]);
            } else {
                s_ts[i] = 0;
                s_len[i] = 0;
            }
        }
        __syncthreads();
        int Lm = s_lmax;
        for (int j = RNDJ; j < Lm; j++) {
#pragma unroll
            for (int e = 0; e < EPB; e++) {
                if (j < s_len[e])
                    sh[e][i] = y[(size_t)(s_ts[e] + j - 1) * HD + i];
            }
            __syncthreads();
            float ar[EPB], az[EPB], an[EPB];
#pragma unroll
            for (int e = 0; e < EPB; e++) { ar[e] = 0.f; az[e] = 0.f; an[e] = 0.f; }
#pragma unroll 4
            for (int k = 0; k < 64; k++) {
                float4 a = w0[k], b = w1[k], cc = w2[k];
#pragma unroll
                for (int e = 0; e < EPB; e++) {
                    float4 hv = *(const float4*)&sh[e][k * 4];
                    ar[e] = fmaf(hv.x, a.x, ar[e]);  ar[e] = fmaf(hv.y, a.y, ar[e]);
                    ar[e] = fmaf(hv.z, a.z, ar[e]);  ar[e] = fmaf(hv.w, a.w, ar[e]);
                    az[e] = fmaf(hv.x, b.x, az[e]);  az[e] = fmaf(hv.y, b.y, az[e]);
                    az[e] = fmaf(hv.z, b.z, az[e]);  az[e] = fmaf(hv.w, b.w, az[e]);
                    an[e] = fmaf(hv.x, cc.x, an[e]); an[e] = fmaf(hv.y, cc.y, an[e]);
                    an[e] = fmaf(hv.z, cc.z, an[e]); an[e] = fmaf(hv.w, cc.w, an[e]);
                }
            }
#pragma unroll
            for (int e = 0; e < EPB; e++) {
                if (j < s_len[e]) {
                    int t = s_ts[e] + j;
                    const float* ig = g_ig + (size_t)t * G3;
                    float r = sigm(ig[i] + ar[e]);
                    float z = sigm(ig[HD + i] + az[e]);
                    float n = tanhs(ig[2 * HD + i] + r * (an[e] + bn));
                    y[(size_t)t * HD + i] = n + z * (sh[e][i] - n);
                }
            }
            __syncthreads();
        }
        __syncthreads();
    }
}

// ---------------- tail: final_state = y[T-1] ----------------
__global__ void k_tail(float* out, int T, long long out_size) {
    long long base = (long long)T * HD;
    if (out_size >= base + HD) {
        int i = threadIdx.x;
        out[base + i] = out[base - HD + i];
    }
}

// ---------------- launch ----------------
extern "C" void kernel_launch(void* const* d_in, const int* in_sizes, int n_in,
                              void* d_out, int out_size) {
    const float* x      = (const float*)d_in[0];
    const float* state  = (const float*)d_in[1];
    const int*   start  = (const int*)d_in[2];
    const float* Wih    = (const float*)d_in[4];
    const float* Whh    = (const float*)d_in[5];
    const float* bias   = (const float*)d_in[6];
    const float* bias_n = (const float*)d_in[7];
    float* out = (float*)d_out;

    int T = in_sizes[2];
    if (T > MAXT) T = MAXT;

    cudaFuncSetAttribute(k_igf, cudaFuncAttributeMaxDynamicSharedMemorySize, HG2_SMEM);
    cudaFuncSetAttribute(k_hg2, cudaFuncAttributeMaxDynamicSharedMemorySize, HG2_SMEM);

    k_split<<<193, 1024>>>(Wih, Whh, start, T);
    k_igf<<<dim3(4, (T + 127) / 128), HG2_THREADS, HG2_SMEM>>>(x, start, bias, bias_n, out);
    k_ep0<<<8, 256>>>(out, state, Whh, bias_n);
    for (int j = 1; j < RNDJ; j++) {
        int maxnj = T / (j + 1) + 1;
        k_hg2<<<dim3(4, (maxnj + 127) / 128), HG2_THREADS, HG2_SMEM>>>(out, bias_n, j);
    }
    k_finish8<<<512, 256>>>(Whh, bias_n, out);
    k_tail<<<1, 256>>>(out, T, (long long)out_size);
}

// round 17
// speedup vs baseline: 1.0845x; 1.0845x over previous
#include <cuda_runtime.h>
#include <cuda_bf16.h>
#include <cstdint>
#include <math.h>

#define MAXT 65536
#define HD   256
#define G3   768
#define NRA  40
#define RNDJ 6        // rounds 0..5 batched; finisher handles j>=6
#define HBINS 2048
#define EPB  8        // episodes per finisher block

// ---------------- device scratch ----------------
__device__ float g_ig[(size_t)MAXT * G3];
__device__ __align__(16) __nv_bfloat16 g_xh[(size_t)MAXT * HD];
__device__ __align__(16) __nv_bfloat16 g_xl[(size_t)MAXT * HD];
__device__ __align__(16) __nv_bfloat16 g_wih_h[G3 * HD];
__device__ __align__(16) __nv_bfloat16 g_wih_l[G3 * HD];
__device__ __align__(16) __nv_bfloat16 g_wq_h[G3 * HD];   // Whh gate-interleaved split
__device__ __align__(16) __nv_bfloat16 g_wq_l[G3 * HD];
__device__ int g_starts[MAXT + 1];
__device__ int g_len[MAXT];
__device__ int g_sorted[MAXT];
__device__ int g_hist[MAXT + 2];
__device__ int g_suffix[MAXT + 2];
__device__ int g_off[MAXT + 2];
__device__ int g_nact[NRA + 2];
__device__ int g_nep;
__device__ int g_start0;

// ---------------- math helpers ----------------
__device__ __forceinline__ float sigm(float x) {
    x = fminf(15.f, fmaxf(-15.f, x));
    return 1.f / (1.f + __expf(-x));
}
__device__ __forceinline__ float tanhs(float x) {
    x = fminf(9.f, fmaxf(-9.f, x));
    float e = __expf(-2.f * x);
    return (1.f - e) / (1.f + e);
}
__device__ __forceinline__ uint32_t smem_u32(const void* p) {
    uint32_t a;
    asm("{ .reg .u64 t; cvta.to.shared.u64 t, %1; cvt.u32.u64 %0, t; }" : "=r"(a) : "l"(p));
    return a;
}
__device__ __forceinline__ void cpa16(uint32_t s, const void* g) {
    asm volatile("cp.async.cg.shared.global [%0], [%1], 16;"
                 :: "r"(s), "l"(g) : "memory");
}
#define CP_COMMIT() asm volatile("cp.async.commit_group;" ::: "memory")
#define CP_WAIT(n)  asm volatile("cp.async.wait_group %0;" :: "n"(n) : "memory")

__device__ __forceinline__ void ldsm4(uint32_t a, uint32_t* r) {
    asm volatile("ldmatrix.sync.aligned.m8n8.x4.shared.b16 {%0,%1,%2,%3}, [%4];"
                 : "=r"(r[0]), "=r"(r[1]), "=r"(r[2]), "=r"(r[3]) : "r"(a));
}
__device__ __forceinline__ void mma16816(float* c, const uint32_t* a,
                                         uint32_t b0, uint32_t b1) {
    asm volatile("mma.sync.aligned.m16n8k16.row.col.f32.bf16.bf16.f32 "
                 "{%0,%1,%2,%3}, {%4,%5,%6,%7}, {%8,%9}, {%0,%1,%2,%3};"
                 : "+f"(c[0]), "+f"(c[1]), "+f"(c[2]), "+f"(c[3])
                 : "r"(a[0]), "r"(a[1]), "r"(a[2]), "r"(a[3]), "r"(b0), "r"(b1));
}

// Fused 3-term chunk MMA, 2 m-subtiles per warp (k_ig). NG = 32-col B groups.
template<int NG>
__device__ __forceinline__ void mma_fused(uint32_t ah, uint32_t al,
                                          uint32_t bh, uint32_t bl,
                                          float (&acc)[2][4 * NG][4],
                                          int lane, int wm, int wn) {
    int arow = wm * 32 + (lane & 7) + (((lane >> 3) & 1) << 3);
    int aks  = (lane >> 4) & 1;
    int axor = arow & 7;
    uint32_t ahB = ah + arow * 128, alB = al + arow * 128;
    int brow0 = (lane & 7) + (((lane >> 4) & 1) << 3);
    int bks  = (lane >> 3) & 1;
#pragma unroll
    for (int ks = 0; ks < 4; ks++) {
        uint32_t au = (uint32_t)(((2 * ks + aks) ^ axor) << 4);
        uint32_t AH0[4], AH1[4], AL0[4], AL1[4];
        ldsm4(ahB + au,        AH0);
        ldsm4(ahB + 2048 + au, AH1);
        ldsm4(alB + au,        AL0);
        ldsm4(alB + 2048 + au, AL1);
#pragma unroll
        for (int g = 0; g < NG; g++) {
            int brow = wn * (32 * NG) + g * 32 + brow0;
            int bxor = brow & 7;
            uint32_t bu = (uint32_t)(((2 * ks + bks) ^ bxor) << 4);
            uint32_t bb = (uint32_t)(brow * 128);
            uint32_t BH0[4], BH1[4], BL0[4], BL1[4];
            ldsm4(bh + bb + bu,        BH0);
            ldsm4(bh + bb + 2048 + bu, BH1);
            ldsm4(bl + bb + bu,        BL0);
            ldsm4(bl + bb + 2048 + bu, BL1);
            int nb = g * 4;
            mma16816(acc[0][nb+0], AH0, BH0[0], BH0[1]);
            mma16816(acc[0][nb+1], AH0, BH0[2], BH0[3]);
            mma16816(acc[0][nb+2], AH0, BH1[0], BH1[1]);
            mma16816(acc[0][nb+3], AH0, BH1[2], BH1[3]);
            mma16816(acc[1][nb+0], AH1, BH0[0], BH0[1]);
            mma16816(acc[1][nb+1], AH1, BH0[2], BH0[3]);
            mma16816(acc[1][nb+2], AH1, BH1[0], BH1[1]);
            mma16816(acc[1][nb+3], AH1, BH1[2], BH1[3]);
            mma16816(acc[0][nb+0], AH0, BL0[0], BL0[1]);
            mma16816(acc[0][nb+1], AH0, BL0[2], BL0[3]);
            mma16816(acc[0][nb+2], AH0, BL1[0], BL1[1]);
            mma16816(acc[0][nb+3], AH0, BL1[2], BL1[3]);
            mma16816(acc[1][nb+0], AH1, BL0[0], BL0[1]);
            mma16816(acc[1][nb+1], AH1, BL0[2], BL0[3]);
            mma16816(acc[1][nb+2], AH1, BL1[0], BL1[1]);
            mma16816(acc[1][nb+3], AH1, BL1[2], BL1[3]);
            mma16816(acc[0][nb+0], AL0, BH0[0], BH0[1]);
            mma16816(acc[0][nb+1], AL0, BH0[2], BH0[3]);
            mma16816(acc[0][nb+2], AL0, BH1[0], BH1[1]);
            mma16816(acc[0][nb+3], AL0, BH1[2], BH1[3]);
            mma16816(acc[1][nb+0], AL1, BH0[0], BH0[1]);
            mma16816(acc[1][nb+1], AL1, BH0[2], BH0[3]);
            mma16816(acc[1][nb+2], AL1, BH1[0], BH1[1]);
            mma16816(acc[1][nb+3], AL1, BH1[2], BH1[3]);
        }
    }
}

// Fused 3-term chunk MMA, ONE 16-row m-subtile per warp (k_hg2, 16 warps).
template<int NG>
__device__ __forceinline__ void mma_fused1(uint32_t ah, uint32_t al,
                                           uint32_t bh, uint32_t bl,
                                           float (&acc)[4 * NG][4],
                                           int lane, int wm, int wn) {
    int arow = wm * 16 + (lane & 7) + (((lane >> 3) & 1) << 3);
    int aks  = (lane >> 4) & 1;
    int axor = arow & 7;
    uint32_t ahB = ah + arow * 128, alB = al + arow * 128;
    int brow0 = (lane & 7) + (((lane >> 4) & 1) << 3);
    int bks  = (lane >> 3) & 1;
#pragma unroll
    for (int ks = 0; ks < 4; ks++) {
        uint32_t au = (uint32_t)(((2 * ks + aks) ^ axor) << 4);
        uint32_t AH0[4], AL0[4];
        ldsm4(ahB + au, AH0);
        ldsm4(alB + au, AL0);
#pragma unroll
        for (int g = 0; g < NG; g++) {
            int brow = wn * (32 * NG) + g * 32 + brow0;
            int bxor = brow & 7;
            uint32_t bu = (uint32_t)(((2 * ks + bks) ^ bxor) << 4);
            uint32_t bb = (uint32_t)(brow * 128);
            uint32_t BH0[4], BH1[4], BL0[4], BL1[4];
            ldsm4(bh + bb + bu,        BH0);
            ldsm4(bh + bb + 2048 + bu, BH1);
            ldsm4(bl + bb + bu,        BL0);
            ldsm4(bl + bb + 2048 + bu, BL1);
            int nb = g * 4;
            mma16816(acc[nb+0], AH0, BH0[0], BH0[1]);
            mma16816(acc[nb+1], AH0, BH0[2], BH0[3]);
            mma16816(acc[nb+2], AH0, BH1[0], BH1[1]);
            mma16816(acc[nb+3], AH0, BH1[2], BH1[3]);
            mma16816(acc[nb+0], AH0, BL0[0], BL0[1]);
            mma16816(acc[nb+1], AH0, BL0[2], BL0[3]);
            mma16816(acc[nb+2], AH0, BL1[0], BL1[1]);
            mma16816(acc[nb+3], AH0, BL1[2], BL1[3]);
            mma16816(acc[nb+0], AL0, BH0[0], BH0[1]);
            mma16816(acc[nb+1], AL0, BH0[2], BH0[3]);
            mma16816(acc[nb+2], AL0, BH1[0], BH1[1]);
            mma16816(acc[nb+3], AL0, BH1[2], BH1[3]);
        }
    }
}

// ---------------- k_ig stage layout: 2 stages x 48KB (tile 128x64, 2 CTAs/SM) -----
#define IGS_AH 0
#define IGS_AL 16384
#define IGS_BH 32768
#define IGS_BL 40960
#define IGS_STRIDE 49152
#define IG_SMEM (2 * IGS_STRIDE)
#define IG_CST 68

// ---------------- k_hg2: 2 stages (A32 32KB + BH 24KB + BL 24KB) + conv + s_t --
#define HG2_A32 0
#define HG2_BH  32768
#define HG2_BL  57344
#define HG2_STRIDE 81920
#define HG2_CAH 163840
#define HG2_CAL 180224
#define HG2_T   196608
#define HG2_SMEM 197120
#define CSTRIDE 196
#define HG2_THREADS 512

// ---------------- setup body (1024-thread block) ----------------
__device__ __forceinline__ int warp_scan_incl(int v, int lane) {
#pragma unroll
    for (int o = 1; o < 32; o <<= 1) {
        int n = __shfl_up_sync(0xFFFFFFFFu, v, o);
        if (lane >= o) v += n;
    }
    return v;
}
__device__ void setup_body(const int* __restrict__ start, int T) {
    __shared__ int s_w[32];
    __shared__ int s_hist[HBINS];
    __shared__ int s_lmax;
    int tid = threadIdx.x, lane = tid & 31, w = tid >> 5;
    int per = (T + 1023) / 1024;
    int b0 = tid * per, b1 = min(T, b0 + per);

    int c = 0;
    for (int t = b0; t < b1; t++)
        if (t == 0 || start[t] != 0) c++;
    int inc = warp_scan_incl(c, lane);
    if (lane == 31) s_w[w] = inc;
    __syncthreads();
    if (w == 0) s_w[lane] = warp_scan_incl(s_w[lane], lane);
    __syncthreads();
    int excl = inc - c + (w ? s_w[w - 1] : 0);
    int nep = s_w[31];
    if (tid == 0) { g_nep = nep; g_start0 = (start[0] != 0); s_lmax = 0; }

    int e = excl;
    for (int t = b0; t < b1; t++)
        if (t == 0 || start[t] != 0) g_starts[e++] = t;
    if (tid == 0) g_starts[nep] = T;
    for (int b = tid; b < HBINS; b += 1024) s_hist[b] = 0;
    __syncthreads();

    for (int e2 = tid; e2 < nep; e2 += 1024) {
        int L = g_starts[e2 + 1] - g_starts[e2];
        g_len[e2] = L;
        if (L < HBINS) atomicAdd(&s_hist[L], 1);
        atomicMax(&s_lmax, L);
    }
    __syncthreads();
    int Lmax = s_lmax;
    int NB = Lmax + 2;

    for (int b = tid; b < NB; b += 1024) g_hist[b] = 0;
    __syncthreads();
    for (int b = tid; b < min(NB, HBINS); b += 1024)
        if (s_hist[b]) g_hist[b] = s_hist[b];
    if (Lmax >= HBINS) {
        __syncthreads();
        for (int e2 = tid; e2 < nep; e2 += 1024) {
            int L = g_len[e2];
            if (L >= HBINS) atomicAdd(&g_hist[L], 1);
        }
    }
    __syncthreads();

    int per2 = (NB + 1023) / 1024;
    int c0 = tid * per2, c1 = min(NB, c0 + per2);
    int s = 0;
    for (int b = c0; b < c1; b++) s += g_hist[b];
    int inc2 = warp_scan_incl(s, lane);
    if (lane == 31) s_w[w] = inc2;
    __syncthreads();
    if (w == 0) s_w[lane] = warp_scan_incl(s_w[lane], lane);
    __syncthreads();
    int incl_full = inc2 + (w ? s_w[w - 1] : 0);
    int total2 = s_w[31];
    int run = total2 - incl_full;
    for (int b = c1 - 1; b >= c0; b--) { run += g_hist[b]; g_suffix[b] = run; }
    __syncthreads();

    for (int b = tid; b <= Lmax; b += 1024) g_off[b] = g_suffix[b + 1];
    for (int j = tid; j <= NRA; j += 1024)
        g_nact[j] = (j + 1 <= Lmax + 1) ? g_suffix[j + 1] : 0;
    __syncthreads();
    for (int e2 = tid; e2 < nep; e2 += 1024) {
        int L = g_len[e2];
        int p = atomicAdd(&g_off[L], 1);
        g_sorted[p] = e2;
    }
}

// ---------------- merged split + setup kernel ----------------
__global__ void __launch_bounds__(1024) k_split(const float* __restrict__ x,
                                                const float* __restrict__ wih,
                                                const float* __restrict__ whh,
                                                const int* __restrict__ start,
                                                int n4, int nxb, int T) {
    int b = blockIdx.x;
    if (b < 192) {
        int i = b * 1024 + threadIdx.x;
        float v = wih[i];
        __nv_bfloat16 h = __float2bfloat16(v);
        g_wih_h[i] = h;
        g_wih_l[i] = __float2bfloat16(v - __bfloat162float(h));
        int q = i >> 8, k = i & 255;
        int nt = q / 192, rem = q % 192;
        int gg = rem >> 6, il = rem & 63;
        float w = whh[(size_t)(gg * 256 + nt * 64 + il) * HD + k];
        __nv_bfloat16 hh = __float2bfloat16(w);
        g_wq_h[i] = hh;
        g_wq_l[i] = __float2bfloat16(w - __bfloat162float(hh));
    } else if (b < 192 + nxb) {
        int v = (b - 192) * 1024 + threadIdx.x;
        if (v >= n4) return;
        float4 a = *(const float4*)(x + (size_t)v * 4);
        __nv_bfloat16 h0 = __float2bfloat16(a.x), h1 = __float2bfloat16(a.y);
        __nv_bfloat16 h2 = __float2bfloat16(a.z), h3 = __float2bfloat16(a.w);
        __nv_bfloat16 l0 = __float2bfloat16(a.x - __bfloat162float(h0));
        __nv_bfloat16 l1 = __float2bfloat16(a.y - __bfloat162float(h1));
        __nv_bfloat16 l2 = __float2bfloat16(a.z - __bfloat162float(h2));
        __nv_bfloat16 l3 = __float2bfloat16(a.w - __bfloat162float(h3));
        __nv_bfloat162* ph = (__nv_bfloat162*)(g_xh + (size_t)v * 4);
        __nv_bfloat162* pl = (__nv_bfloat162*)(g_xl + (size_t)v * 4);
        ph[0] = __halves2bfloat162(h0, h1); ph[1] = __halves2bfloat162(h2, h3);
        pl[0] = __halves2bfloat162(l0, l1); pl[1] = __halves2bfloat162(l2, l3);
    } else {
        setup_body(start, T);
    }
}

// ---------------- igates GEMM (2-stage, 128x64 tile, 2 CTAs/SM) ----------------
__device__ __forceinline__ void ig_issue(uint32_t sb, int stage, int c,
                                         int m0, int n0, int T, int tid) {
    uint32_t st = sb + stage * IGS_STRIDE;
    int cb = c * 64;
#pragma unroll
    for (int v = tid; v < 1024; v += 256) {
        int r = v >> 3, u = v & 7;
        int row = min(m0 + r, T - 1);
        uint32_t off = (uint32_t)(r * 128 + (((u ^ (r & 7))) << 4));
        size_t src = (size_t)row * HD + cb + u * 8;
        cpa16(st + IGS_AH + off, g_xh + src);
        cpa16(st + IGS_AL + off, g_xl + src);
    }
#pragma unroll
    for (int v = tid; v < 512; v += 256) {
        int r = v >> 3, u = v & 7;
        uint32_t off = (uint32_t)(r * 128 + (((u ^ (r & 7))) << 4));
        size_t src = (size_t)(n0 + r) * HD + cb + u * 8;
        cpa16(st + IGS_BH + off, g_wih_h + src);
        cpa16(st + IGS_BL + off, g_wih_l + src);
    }
    CP_COMMIT();
}
__global__ void __launch_bounds__(256, 2) k_ig(const float* __restrict__ bias, int T) {
    extern __shared__ __align__(128) char smem[];
    uint32_t sb = smem_u32(smem);
    int tid = threadIdx.x, lane = tid & 31, wid = tid >> 5;
    int wm = wid >> 1, wn = wid & 1;
    int n0 = blockIdx.x * 64, m0 = blockIdx.y * 128;

    float acc[2][4][4];
#pragma unroll
    for (int a = 0; a < 2; a++)
#pragma unroll
        for (int b = 0; b < 4; b++)
#pragma unroll
            for (int cdx = 0; cdx < 4; cdx++) acc[a][b][cdx] = 0.f;

    ig_issue(sb, 0, 0, m0, n0, T, tid);
    ig_issue(sb, 1, 1, m0, n0, T, tid);

    CP_WAIT(1); __syncthreads();
    {
        uint32_t st = sb;
        mma_fused<1>(st + IGS_AH, st + IGS_AL, st + IGS_BH, st + IGS_BL, acc, lane, wm, wn);
    }
    __syncthreads();
    ig_issue(sb, 0, 2, m0, n0, T, tid);

    CP_WAIT(1); __syncthreads();
    {
        uint32_t st = sb + IGS_STRIDE;
        mma_fused<1>(st + IGS_AH, st + IGS_AL, st + IGS_BH, st + IGS_BL, acc, lane, wm, wn);
    }
    __syncthreads();
    ig_issue(sb, 1, 3, m0, n0, T, tid);

    CP_WAIT(1); __syncthreads();
    {
        uint32_t st = sb;
        mma_fused<1>(st + IGS_AH, st + IGS_AL, st + IGS_BH, st + IGS_BL, acc, lane, wm, wn);
    }
    CP_WAIT(0); __syncthreads();
    {
        uint32_t st = sb + IGS_STRIDE;
        mma_fused<1>(st + IGS_AH, st + IGS_AL, st + IGS_BH, st + IGS_BL, acc, lane, wm, wn);
    }
    __syncthreads();

    float* C = (float*)smem;
#pragma unroll
    for (int nt = 0; nt < 4; nt++) {
        int col = wn * 32 + nt * 8 + (lane & 3) * 2;
#pragma unroll
        for (int mt = 0; mt < 2; mt++) {
            int row = wm * 32 + mt * 16 + (lane >> 2);
            *(float2*)&C[row * IG_CST + col] =
                make_float2(acc[mt][nt][0], acc[mt][nt][1]);
            *(float2*)&C[(row + 8) * IG_CST + col] =
                make_float2(acc[mt][nt][2], acc[mt][nt][3]);
        }
    }
    __syncthreads();
#pragma unroll
    for (int idx = tid; idx < 2048; idx += 256) {
        int row = idx >> 4, q = idx & 15;
        if (m0 + row >= T) continue;
        float4 cv = *(const float4*)&C[row * IG_CST + q * 4];
        float4 bv = *(const float4*)(bias + n0 + q * 4);
        *(float4*)(g_ig + (size_t)(m0 + row) * G3 + n0 + q * 4) =
            make_float4(cv.x + bv.x, cv.y + bv.y, cv.z + bv.z, cv.w + bv.w);
    }
}

// ---------------- fused round kernel (512 threads, 16 warps, 8m x 2n) -----------
__device__ __forceinline__ void hg2_issue(uint32_t sb, char* smem, int stage, int c,
                                          const float* y, int nt, int tid) {
    uint32_t st = sb + stage * HG2_STRIDE;
    const int* s_t = (const int*)(smem + HG2_T);
    int cb = c * 64;
#pragma unroll
    for (int v = tid; v < 2048; v += HG2_THREADS) {
        int r = v >> 4, u = v & 15;
        const float* src = y + (size_t)(s_t[r] - 1) * HD + cb + u * 4;
        cpa16(st + HG2_A32 + r * 256 + u * 16, src);
    }
#pragma unroll
    for (int v = tid; v < 1536; v += HG2_THREADS) {
        int r = v >> 3, u = v & 7;
        uint32_t off = (uint32_t)(r * 128 + (((u ^ (r & 7))) << 4));
        size_t src = (size_t)(nt * 192 + r) * HD + cb + u * 8;
        cpa16(st + HG2_BH + off, g_wq_h + src);
        cpa16(st + HG2_BL + off, g_wq_l + src);
    }
    CP_COMMIT();
}
__device__ __forceinline__ void hg2_convert(char* smem, int stage, int tid) {
    const float* a32 = (const float*)(smem + stage * HG2_STRIDE + HG2_A32);
#pragma unroll
    for (int v = tid; v < 1024; v += HG2_THREADS) {
        int r = v >> 3, u = v & 7;
        float4 f0 = *(const float4*)(a32 + r * 64 + u * 8);
        float4 f1 = *(const float4*)(a32 + r * 64 + u * 8 + 4);
        float fv[8] = {f0.x, f0.y, f0.z, f0.w, f1.x, f1.y, f1.z, f1.w};
        __nv_bfloat16 hi[8], lo[8];
#pragma unroll
        for (int q = 0; q < 8; q++) {
            hi[q] = __float2bfloat16(fv[q]);
            lo[q] = __float2bfloat16(fv[q] - __bfloat162float(hi[q]));
        }
        uint32_t off = (uint32_t)(r * 128 + (((u ^ (r & 7))) << 4));
        *(uint4*)(smem + HG2_CAH + off) = *(const uint4*)hi;
        *(uint4*)(smem + HG2_CAL + off) = *(const uint4*)lo;
    }
}
__global__ void __launch_bounds__(HG2_THREADS, 1) k_hg2(float* __restrict__ y,
                                                        const float* __restrict__ bias_n,
                                                        int j) {
    extern __shared__ __align__(128) char smem[];
    uint32_t sb = smem_u32(smem);
    int* s_t = (int*)(smem + HG2_T);
    int nj = g_nact[j];
    int mt0 = blockIdx.y * 128;
    if (mt0 >= nj) return;
    int tid = threadIdx.x, lane = tid & 31, wid = tid >> 5;
    int wm = wid >> 1, wn = wid & 1;
    int nt = blockIdx.x;

    if (tid < 128) {
        int m = mt0 + tid;
        s_t[tid] = (m < nj) ? (g_starts[g_sorted[m]] + j) : 1;
    }
    __syncthreads();

    float acc[12][4];
#pragma unroll
    for (int b = 0; b < 12; b++)
#pragma unroll
        for (int cdx = 0; cdx < 4; cdx++) acc[b][cdx] = 0.f;

    hg2_issue(sb, smem, 0, 0, y, nt, tid);
    hg2_issue(sb, smem, 1, 1, y, nt, tid);

    CP_WAIT(1); __syncthreads();
    hg2_convert(smem, 0, tid); __syncthreads();
    mma_fused1<3>(sb + HG2_CAH, sb + HG2_CAL,
                  sb + 0 * HG2_STRIDE + HG2_BH, sb + 0 * HG2_STRIDE + HG2_BL,
                  acc, lane, wm, wn);
    __syncthreads();
    hg2_issue(sb, smem, 0, 2, y, nt, tid);

    CP_WAIT(1); __syncthreads();
    hg2_convert(smem, 1, tid); __syncthreads();
    mma_fused1<3>(sb + HG2_CAH, sb + HG2_CAL,
                  sb + 1 * HG2_STRIDE + HG2_BH, sb + 1 * HG2_STRIDE + HG2_BL,
                  acc, lane, wm, wn);
    __syncthreads();
    hg2_issue(sb, smem, 1, 3, y, nt, tid);

    CP_WAIT(1); __syncthreads();
    hg2_convert(smem, 0, tid); __syncthreads();
    mma_fused1<3>(sb + HG2_CAH, sb + HG2_CAL,
                  sb + 0 * HG2_STRIDE + HG2_BH, sb + 0 * HG2_STRIDE + HG2_BL,
                  acc, lane, wm, wn);

    CP_WAIT(0); __syncthreads();
    hg2_convert(smem, 1, tid); __syncthreads();
    mma_fused1<3>(sb + HG2_CAH, sb + HG2_CAL,
                  sb + 1 * HG2_STRIDE + HG2_BH, sb + 1 * HG2_STRIDE + HG2_BL,
                  acc, lane, wm, wn);
    __syncthreads();

    float* C = (float*)smem;
#pragma unroll
    for (int ntv = 0; ntv < 12; ntv++) {
        int g = ntv >> 2, ntl = ntv & 3;
        int col = wn * 96 + g * 32 + ntl * 8 + (lane & 3) * 2;
        int row = wm * 16 + (lane >> 2);
        C[row * CSTRIDE + col]           = acc[ntv][0];
        C[row * CSTRIDE + col + 1]       = acc[ntv][1];
        C[(row + 8) * CSTRIDE + col]     = acc[ntv][2];
        C[(row + 8) * CSTRIDE + col + 1] = acc[ntv][3];
    }
    __syncthreads();

#pragma unroll 1
    for (int idx = tid; idx < 2048; idx += HG2_THREADS) {
        int row = idx >> 4, q4 = idx & 15;
        if (mt0 + row >= nj) continue;
        int t = s_t[row];
        int i = nt * 64 + q4 * 4;
        const float* cr = C + row * CSTRIDE + q4 * 4;
        float4 rp = *(const float4*)(cr);
        float4 zp = *(const float4*)(cr + 64);
        float4 np = *(const float4*)(cr + 128);
        const float* igrow = g_ig + (size_t)t * G3;
        float4 igr = *(const float4*)(igrow + i);
        float4 igz = *(const float4*)(igrow + HD + i);
        float4 ign = *(const float4*)(igrow + 2 * HD + i);
        float4 h4  = *(const float4*)(y + (size_t)(t - 1) * HD + i);
        float4 bn4 = *(const float4*)(bias_n + i);
        float rv[4] = {rp.x, rp.y, rp.z, rp.w};
        float zv[4] = {zp.x, zp.y, zp.z, zp.w};
        float nv[4] = {np.x, np.y, np.z, np.w};
        float ir[4] = {igr.x, igr.y, igr.z, igr.w};
        float iz[4] = {igz.x, igz.y, igz.z, igz.w};
        float in_[4] = {ign.x, ign.y, ign.z, ign.w};
        float hv[4] = {h4.x, h4.y, h4.z, h4.w};
        float bv[4] = {bn4.x, bn4.y, bn4.z, bn4.w};
        float o[4];
#pragma unroll
        for (int u = 0; u < 4; u++) {
            float r = sigm(ir[u] + rv[u]);
            float z = sigm(iz[u] + zv[u]);
            float n = tanhs(in_[u] + r * (nv[u] + bv[u]));
            o[u] = n + z * (hv[u] - n);
        }
        *(float4*)(y + (size_t)t * HD + i) = make_float4(o[0], o[1], o[2], o[3]);
    }
}

// ---------------- round-0 gates (h=0) + embedded ep0 (h=state) -----------------
__global__ void __launch_bounds__(256) k_gates0f(float* __restrict__ y,
                                                 const float* __restrict__ state,
                                                 const float* __restrict__ Whh,
                                                 const float* __restrict__ bias_n) {
    if (blockIdx.x < 8 && !g_start0) {
        __shared__ float sh[HD];
        int tid = threadIdx.x;
        sh[tid] = state[tid];
        __syncthreads();
        int u = tid >> 3, s = tid & 7;
        int i = blockIdx.x * 32 + u;
        const float4* h4 = (const float4*)(sh + s * 32);
        float p[3];
#pragma unroll
        for (int g = 0; g < 3; g++) {
            const float4* w = (const float4*)(Whh + (size_t)(g * HD + i) * HD + s * 32);
            float acc = 0.f;
#pragma unroll
            for (int k = 0; k < 8; k++) {
                float4 hv = h4[k], wv = w[k];
                acc = fmaf(hv.x, wv.x, acc); acc = fmaf(hv.y, wv.y, acc);
                acc = fmaf(hv.z, wv.z, acc); acc = fmaf(hv.w, wv.w, acc);
            }
#pragma unroll
            for (int o = 4; o >= 1; o >>= 1)
                acc += __shfl_down_sync(0xFFFFFFFFu, acc, o);
            p[g] = acc;
        }
        if (s == 0) {
            const float* ig = g_ig;
            float h = sh[i];
            float r = sigm(ig[i] + p[0]);
            float z = sigm(ig[HD + i] + p[1]);
            float n = tanhs(ig[2 * HD + i] + r * (p[2] + bias_n[i]));
            y[i] = n + z * (h - n);
        }
        __syncthreads();
    }
    int nj = g_nact[0];
    int rloc = threadIdx.x >> 6;
    int q = (threadIdx.x & 63) * 4;
    float4 bn4 = *(const float4*)(bias_n + q);
    for (int base = blockIdx.x * 4; base < nj; base += gridDim.x * 4) {
        int m = base + rloc;
        if (m >= nj) continue;
        int e = g_sorted[m];
        if (e == 0 && !g_start0) continue;
        int t = g_starts[e];
        const float* ig = g_ig + (size_t)t * G3;
        float4 ir = *(const float4*)(ig + q);
        float4 iz = *(const float4*)(ig + HD + q);
        float4 in4 = *(const float4*)(ig + 2 * HD + q);
        float irv[4] = {ir.x, ir.y, ir.z, ir.w};
        float izv[4] = {iz.x, iz.y, iz.z, iz.w};
        float inv[4] = {in4.x, in4.y, in4.z, in4.w};
        float bnv[4] = {bn4.x, bn4.y, bn4.z, bn4.w};
        float o[4];
#pragma unroll
        for (int u = 0; u < 4; u++) {
            float r = sigm(irv[u]);
            float z = sigm(izv[u]);
            float n = tanhs(inv[u] + r * bnv[u]);
            o[u] = n * (1.f - z);
        }
        *(float4*)(y + (size_t)t * HD + q) = make_float4(o[0], o[1], o[2], o[3]);
    }
}

// ---------------- finisher: 8 sorted-adjacent episodes per block, lockstep ------
__global__ void __launch_bounds__(256) k_finish8(const float* __restrict__ Whh,
                                                 const float* __restrict__ bias_n,
                                                 float* y) {
    int nover = g_nact[RNDJ];
    __shared__ __align__(16) float sh[EPB][HD];
    __shared__ int s_ts[EPB], s_len[EPB], s_lmax;
    int i = threadIdx.x;
    const float4* w0 = (const float4*)(Whh + (size_t)i * HD);
    const float4* w1 = (const float4*)(Whh + (size_t)(HD + i) * HD);
    const float4* w2 = (const float4*)(Whh + (size_t)(2 * HD + i) * HD);
    float bn = bias_n[i];

    for (int g0 = blockIdx.x * EPB; g0 < nover; g0 += gridDim.x * EPB) {
        if (i == 0) s_lmax = 0;
        __syncthreads();
        if (i < EPB) {
            int idx = g0 + i;
            if (idx < nover) {
                int e = g_sorted[idx];
                s_ts[i] = g_starts[e];
                s_len[i] = g_len[e];
                atomicMax(&s_lmax, g_len[e]);
            } else {
                s_ts[i] = 0;
                s_len[i] = 0;
            }
        }
        __syncthreads();
        int Lm = s_lmax;
        for (int j = RNDJ; j < Lm; j++) {
#pragma unroll
            for (int e = 0; e < EPB; e++) {
                if (j < s_len[e])
                    sh[e][i] = y[(size_t)(s_ts[e] + j - 1) * HD + i];
            }
            __syncthreads();
            float ar[EPB], az[EPB], an[EPB];
#pragma unroll
            for (int e = 0; e < EPB; e++) { ar[e] = 0.f; az[e] = 0.f; an[e] = 0.f; }
#pragma unroll 4
            for (int k = 0; k < 64; k++) {
                float4 a = w0[k], b = w1[k], cc = w2[k];
#pragma unroll
                for (int e = 0; e < EPB; e++) {
                    float4 hv = *(const float4*)&sh[e][k * 4];
                    ar[e] = fmaf(hv.x, a.x, ar[e]);  ar[e] = fmaf(hv.y, a.y, ar[e]);
                    ar[e] = fmaf(hv.z, a.z, ar[e]);  ar[e] = fmaf(hv.w, a.w, ar[e]);
                    az[e] = fmaf(hv.x, b.x, az[e]);  az[e] = fmaf(hv.y, b.y, az[e]);
                    az[e] = fmaf(hv.z, b.z, az[e]);  az[e] = fmaf(hv.w, b.w, az[e]);
                    an[e] = fmaf(hv.x, cc.x, an[e]); an[e] = fmaf(hv.y, cc.y, an[e]);
                    an[e] = fmaf(hv.z, cc.z, an[e]); an[e] = fmaf(hv.w, cc.w, an[e]);
                }
            }
#pragma unroll
            for (int e = 0; e < EPB; e++) {
                if (j < s_len[e]) {
                    int t = s_ts[e] + j;
                    const float* ig = g_ig + (size_t)t * G3;
                    float r = sigm(ig[i] + ar[e]);
                    float z = sigm(ig[HD + i] + az[e]);
                    float n = tanhs(ig[2 * HD + i] + r * (an[e] + bn));
                    y[(size_t)t * HD + i] = n + z * (sh[e][i] - n);
                }
            }
            __syncthreads();
        }
        __syncthreads();
    }
}

// ---------------- tail: final_state = y[T-1] ----------------
__global__ void k_tail(float* out, int T, long long out_size) {
    long long base = (long long)T * HD;
    if (out_size >= base + HD) {
        int i = threadIdx.x;
        out[base + i] = out[base - HD + i];
    }
}

// ---------------- launch ----------------
extern "C" void kernel_launch(void* const* d_in, const int* in_sizes, int n_in,
                              void* d_out, int out_size) {
    const float* x      = (const float*)d_in[0];
    const float* state  = (const float*)d_in[1];
    const int*   start  = (const int*)d_in[2];
    const float* Wih    = (const float*)d_in[4];
    const float* Whh    = (const float*)d_in[5];
    const float* bias   = (const float*)d_in[6];
    const float* bias_n = (const float*)d_in[7];
    float* out = (float*)d_out;

    int T = in_sizes[2];
    if (T > MAXT) T = MAXT;

    cudaFuncSetAttribute(k_ig, cudaFuncAttributeMaxDynamicSharedMemorySize, IG_SMEM);
    cudaFuncSetAttribute(k_hg2, cudaFuncAttributeMaxDynamicSharedMemorySize, HG2_SMEM);

    int n4 = T * HD / 4;
    int nxb = (n4 + 1023) / 1024;
    k_split<<<192 + nxb + 1, 1024>>>(x, Wih, Whh, start, n4, nxb, T);
    k_ig<<<dim3(12, (T + 127) / 128), 256, IG_SMEM>>>(bias, T);
    k_gates0f<<<8192, 256>>>(out, state, Whh, bias_n);
    for (int j = 1; j < RNDJ; j++) {
        int maxnj = T / (j + 1) + 1;
        k_hg2<<<dim3(4, (maxnj + 127) / 128), HG2_THREADS, HG2_SMEM>>>(out, bias_n, j);
    }
    k_finish8<<<512, 256>>>(Whh, bias_n, out);
    k_tail<<<1, 256>>>(out, T, (long long)out_size);
}